// round 16
// baseline (speedup 1.0000x reference)
#include <cuda_runtime.h>
#include <cuda_bf16.h>
#include <math.h>
#include <cstdint>

#define BATCH 128
#define FEAT  1024
#define CLS   500
#define HID   512

#define AROWS 640                // 128 img + 500 attr + pad
#define KSTOR 2048               // stored: [hi(1024), lo(1024)]
#define NSLAB 48                 // virtual K = 3072: hi.hi x16, lo.hi x16, hi.lo x16

// ---------------- device scratch ----------------
__device__ __align__(16) unsigned short g_A[AROWS * KSTOR];  // bf16 bits [hi|lo]
__device__ __align__(16) unsigned short g_B[2][HID * KSTOR]; // [W1 half][n][hi|lo]
__device__ float g_imgT[HID * BATCH];                        // [h][b], b1 folded
__device__ float g_attr[512 * HID];                          // [c][h]

// ---------------- warp-MMA primitives (baseline ISA, sm_80+) ----------------
__device__ __forceinline__ uint32_t smem_u32(const void* p) {
    uint32_t a;
    asm("{ .reg .u64 t; cvta.to.shared.u64 t, %1; cvt.u32.u64 %0, t; }" : "=r"(a) : "l"(p));
    return a;
}
__device__ __forceinline__ void ldsm_x4(uint32_t* r, uint32_t addr) {
    asm volatile("ldmatrix.sync.aligned.m8n8.x4.shared.b16 {%0,%1,%2,%3}, [%4];"
                 : "=r"(r[0]), "=r"(r[1]), "=r"(r[2]), "=r"(r[3]) : "r"(addr));
}
__device__ __forceinline__ void mma_bf16(float* c, const uint32_t* a, const uint32_t* b) {
    asm volatile("mma.sync.aligned.m16n8k16.row.col.f32.bf16.bf16.f32 "
        "{%0,%1,%2,%3}, {%4,%5,%6,%7}, {%8,%9}, {%0,%1,%2,%3};"
        : "+f"(c[0]), "+f"(c[1]), "+f"(c[2]), "+f"(c[3])
        : "r"(a[0]), "r"(a[1]), "r"(a[2]), "r"(a[3]), "r"(b[0]), "r"(b[1]));
}

// slab -> k offsets in stored [hi|lo] arrays (virtual order: hi.hi, lo.hi, hi.lo)
__device__ __forceinline__ int a_koff(int s) {
    return (s < 16) ? s * 64 : (s < 32) ? 1024 + (s - 16) * 64 : (s - 32) * 64;
}
__device__ __forceinline__ int b_koff(int s) {
    return (s < 32) ? (s & 15) * 64 : 1024 + (s - 32) * 64;
}

// ---------------------------------------------------------------------
// fp32 -> bf16 hi/lo operands.
// ---------------------------------------------------------------------
__device__ __forceinline__ void split4(float4 v, uint2& hi, uint2& lo) {
    const float* f = (const float*)&v;
    unsigned short h[4], l[4];
    #pragma unroll
    for (int i = 0; i < 4; i++) {
        __nv_bfloat16 hb = __float2bfloat16(f[i]);
        h[i] = __bfloat16_as_ushort(hb);
        l[i] = __bfloat16_as_ushort(__float2bfloat16(f[i] - __bfloat162float(hb)));
    }
    hi.x = (uint32_t)h[0] | ((uint32_t)h[1] << 16);
    hi.y = (uint32_t)h[2] | ((uint32_t)h[3] << 16);
    lo.x = (uint32_t)l[0] | ((uint32_t)l[1] << 16);
    lo.y = (uint32_t)l[2] | ((uint32_t)l[3] << 16);
}

#define CONV_A (AROWS * 256)
#define CONV_B (2 * HID * 256)

__global__ __launch_bounds__(256) void convert_bf16(
    const float* __restrict__ img, const float* __restrict__ attr,
    const float* __restrict__ W1)
{
    const int idx = blockIdx.x * 256 + threadIdx.x;
    if (idx < CONV_A) {
        const int r = idx >> 8, k = (idx & 255) * 4;
        float4 v = make_float4(0.f, 0.f, 0.f, 0.f);
        if (r < 128)      v = *(const float4*)&img[(size_t)r * FEAT + k];
        else if (r < 628) v = *(const float4*)&attr[(size_t)(r - 128) * FEAT + k];
        uint2 hi, lo; split4(v, hi, lo);
        *(uint2*)&g_A[(size_t)r * KSTOR + k]        = hi;
        *(uint2*)&g_A[(size_t)r * KSTOR + 1024 + k] = lo;
    } else if (idx < CONV_A + CONV_B) {
        int j = idx - CONV_A;
        const int half = j >= HID * 256; if (half) j -= HID * 256;
        const int n = j >> 8, k = (j & 255) * 4;
        float4 v = *(const float4*)&W1[(size_t)n * (2 * FEAT) + half * FEAT + k];
        uint2 hi, lo; split4(v, hi, lo);
        unsigned short* Bp = g_B[half];
        *(uint2*)&Bp[(size_t)n * KSTOR + k]        = hi;
        *(uint2*)&Bp[(size_t)n * KSTOR + 1024 + k] = lo;
    }
}

// ---------------------------------------------------------------------
// HMMA GEMM: D[64m x 32n] per block, 128 threads (2x2 warps, warp 32m x 16n).
// by 0..1: img rows -> g_imgT [h][b] (+b1); by 2..9: attr rows -> g_attr [c][h].
// 48 virtual K-slabs of 64 via slab->offset mapping (hi/lo segments).
// ---------------------------------------------------------------------
#define BLKM 64
#define BLKN 32
#define PADK 72          // 144B row stride: 16B-mult, conflict-free ldsm

__global__ __launch_bounds__(128) void gemm_mma(const float* __restrict__ b1)
{
    __shared__ __align__(16) unsigned short As[2][BLKM][PADK];
    __shared__ __align__(16) unsigned short Bs[2][BLKN][PADK];

    const int tid  = threadIdx.x;
    const int lane = tid & 31;
    const int warp = tid >> 5;
    const int wm   = warp & 1;
    const int wn   = warp >> 1;
    const int by   = blockIdx.y;      // 10
    const int bx   = blockIdx.x;      // 16
    const bool is_img = (by < 2);

    const unsigned short* Aq = g_A + (size_t)(by * BLKM) * KSTOR;
    const unsigned short* Bq = g_B[is_img ? 0 : 1] + (size_t)(bx * BLKN) * KSTOR;

    const uint32_t asb = smem_u32(As);
    const uint32_t bsb = smem_u32(Bs);
    uint32_t aRow[2];
    #pragma unroll
    for (int mi = 0; mi < 2; mi++)
        aRow[mi] = (uint32_t)((wm * 32 + mi * 16 + (lane & 15)) * (PADK * 2) + (lane >> 4) * 16);
    const int n_l = wn * 16 + (lane & 7) + ((lane >> 4) << 3);
    const uint32_t bRow = (uint32_t)(n_l * (PADK * 2) + ((lane >> 3) & 1) * 16);

    float acc[2][2][4];
    #pragma unroll
    for (int i = 0; i < 2; i++)
        #pragma unroll
        for (int j = 0; j < 2; j++)
            #pragma unroll
            for (int q = 0; q < 4; q++) acc[i][j][q] = 0.f;

    uint4 a_pf[4], b_pf[2];
    {   // prefetch slab 0 (a_koff(0)=0, b_koff(0)=0)
        #pragma unroll
        for (int i = 0; i < 4; i++) {
            const int id = i * 128 + tid;
            a_pf[i] = *(const uint4*)&Aq[(size_t)(id >> 3) * KSTOR + (id & 7) * 8];
        }
        #pragma unroll
        for (int i = 0; i < 2; i++) {
            const int id = i * 128 + tid;
            b_pf[i] = *(const uint4*)&Bq[(size_t)(id >> 3) * KSTOR + (id & 7) * 8];
        }
    }

    for (int it = 0; it < NSLAB; it++) {
        const int p = it & 1;
        #pragma unroll
        for (int i = 0; i < 4; i++) {
            const int id = i * 128 + tid;
            *(uint4*)&As[p][id >> 3][(id & 7) * 8] = a_pf[i];
        }
        #pragma unroll
        for (int i = 0; i < 2; i++) {
            const int id = i * 128 + tid;
            *(uint4*)&Bs[p][id >> 3][(id & 7) * 8] = b_pf[i];
        }
        __syncthreads();

        if (it + 1 < NSLAB) {
            const int ka = a_koff(it + 1), kb = b_koff(it + 1);
            #pragma unroll
            for (int i = 0; i < 4; i++) {
                const int id = i * 128 + tid;
                a_pf[i] = *(const uint4*)&Aq[(size_t)(id >> 3) * KSTOR + ka + (id & 7) * 8];
            }
            #pragma unroll
            for (int i = 0; i < 2; i++) {
                const int id = i * 128 + tid;
                b_pf[i] = *(const uint4*)&Bq[(size_t)(id >> 3) * KSTOR + kb + (id & 7) * 8];
            }
        }

        const uint32_t aBase = asb + (uint32_t)p * sizeof(As[0]);
        const uint32_t bBase = bsb + (uint32_t)p * sizeof(Bs[0]);
        #pragma unroll
        for (int ks = 0; ks < 4; ks++) {
            uint32_t af0[4], af1[4], bf[4];
            ldsm_x4(af0, aBase + aRow[0] + ks * 32);
            ldsm_x4(af1, aBase + aRow[1] + ks * 32);
            ldsm_x4(bf, bBase + bRow + ks * 32);
            mma_bf16(acc[0][0], af0, bf + 0);
            mma_bf16(acc[0][1], af0, bf + 2);
            mma_bf16(acc[1][0], af1, bf + 0);
            mma_bf16(acc[1][1], af1, bf + 2);
        }
        __syncthreads();
    }

    // writeout
    const int g  = lane >> 2;
    const int tc = (lane & 3) * 2;
    #pragma unroll
    for (int mi = 0; mi < 2; mi++) {
        #pragma unroll
        for (int half = 0; half < 2; half++) {
            const int row = by * BLKM + wm * 32 + mi * 16 + g + half * 8;
            #pragma unroll
            for (int nj = 0; nj < 2; nj++) {
                const int h = bx * BLKN + wn * 16 + nj * 8 + tc;
                const float v0 = acc[mi][nj][half * 2 + 0];
                const float v1 = acc[mi][nj][half * 2 + 1];
                if (is_img) {
                    g_imgT[(h + 0) * BATCH + row] = v0 + __ldg(&b1[h]);
                    g_imgT[(h + 1) * BATCH + row] = v1 + __ldg(&b1[h + 1]);
                } else {
                    const int c = row - 128;
                    g_attr[(size_t)c * HID + h]     = v0;
                    g_attr[(size_t)c * HID + h + 1] = v1;
                }
            }
        }
    }
}

// ---------------------------------------------------------------------
// Fused relscore + sigmoid:
// out[b, c0..c0+3] = sigmoid(b2 + sum_h relu(imgT[h,b] + attr[c,h]) * W2[h])
// 125 blocks x 256 threads: half = tid>>7 handles h in [half*256, +256),
// b = tid&127; smem cross-reduce between halves, float4 store.
// ---------------------------------------------------------------------
#define CT 4
#define HHALF 256

__global__ __launch_bounds__(256) void relscore_out(
    float* __restrict__ out, const float* __restrict__ W2,
    const float* __restrict__ b2)
{
    __shared__ float attrS[2][HHALF][CT];   // [half][h][c] 16B rows
    __shared__ float w2s[HID];
    __shared__ float accS[128][CT];

    const int tid  = threadIdx.x;
    const int half = tid >> 7;
    const int b    = tid & 127;
    const int c0   = blockIdx.x * CT;
    const int h0   = half * HHALF;

    // attr tile: each half-group loads its own h range, coalesced over h
    #pragma unroll
    for (int cc = 0; cc < CT; cc++) {
        #pragma unroll
        for (int j = 0; j < 2; j++) {
            const int hh = j * 128 + b;
            attrS[half][hh][cc] = g_attr[(size_t)(c0 + cc) * HID + h0 + hh];
        }
    }
    #pragma unroll
    for (int j = 0; j < 2; j++)
        w2s[h0 + j * 128 + b] = W2[h0 + j * 128 + b];
    __syncthreads();

    float acc[CT] = {0.f, 0.f, 0.f, 0.f};
    const float* ip = g_imgT + (size_t)h0 * BATCH + b;

    #pragma unroll 8
    for (int hh = 0; hh < HHALF; hh++) {
        const float iv = ip[(size_t)hh * BATCH];    // coalesced over b
        const float w  = w2s[h0 + hh];
        float4 a = *(float4*)&attrS[half][hh][0];   // broadcast
        acc[0] += fmaxf(iv + a.x, 0.f) * w;
        acc[1] += fmaxf(iv + a.y, 0.f) * w;
        acc[2] += fmaxf(iv + a.z, 0.f) * w;
        acc[3] += fmaxf(iv + a.w, 0.f) * w;
    }

    if (half == 1) {
        #pragma unroll
        for (int cc = 0; cc < CT; cc++) accS[b][cc] = acc[cc];
    }
    __syncthreads();
    if (half == 0) {
        const float bias = b2[0];
        float4 r;
        float* rv = (float*)&r;
        #pragma unroll
        for (int cc = 0; cc < CT; cc++) {
            const float s = acc[cc] + accS[b][cc] + bias;
            rv[cc] = 1.f / (1.f + __expf(-s));
        }
        *(float4*)&out[(size_t)b * CLS + c0] = r;   // aligned: CLS%4==0
    }
}

// ---------------------------------------------------------------------
extern "C" void kernel_launch(void* const* d_in, const int* in_sizes, int n_in,
                              void* d_out, int out_size)
{
    const float* img  = (const float*)d_in[0];
    const float* attr = (const float*)d_in[1];
    const float* W1   = (const float*)d_in[2];
    const float* b1   = (const float*)d_in[3];
    const float* W2   = (const float*)d_in[4];
    const float* b2   = (const float*)d_in[5];
    float* out = (float*)d_out;

    convert_bf16<<<(CONV_A + CONV_B + 255) / 256, 256>>>(img, attr, W1);
    gemm_mma<<<dim3(HID / BLKN, AROWS / BLKM), 128>>>(b1);   // 160 blocks
    relscore_out<<<CLS / CT, 256>>>(out, W2, b2);            // 125 blocks
}

// round 17
// speedup vs baseline: 1.4763x; 1.4763x over previous
#include <cuda_runtime.h>
#include <cuda_bf16.h>
#include <math.h>
#include <cstdint>

#define BATCH 128
#define FEAT  1024
#define CLS   500
#define HID   512

#define HSPLIT 4
#define HCH    (HID / HSPLIT)    // 128

#define AROWS 640                // 128 img + 500 attr + pad
#define KP    3072               // augmented K: A=[hi,lo,hi], B=[hi,hi,lo]

// ---------------- device scratch ----------------
__device__ __align__(16) unsigned short g_A[AROWS * KP];     // bf16 bits
__device__ __align__(16) unsigned short g_B[2][HID * KP];    // [W1 half][n][k']
__device__ float g_imgT[HID * BATCH];                        // [h][b], b1 folded
__device__ float g_attr[512 * HID];                          // [c][h]
__device__ float g_part[HSPLIT][512 * BATCH];                // relscore partials

// ---------------- warp-MMA primitives (baseline ISA, sm_80+) ----------------
__device__ __forceinline__ uint32_t smem_u32(const void* p) {
    uint32_t a;
    asm("{ .reg .u64 t; cvta.to.shared.u64 t, %1; cvt.u32.u64 %0, t; }" : "=r"(a) : "l"(p));
    return a;
}
__device__ __forceinline__ void ldsm_x4(uint32_t* r, uint32_t addr) {
    asm volatile("ldmatrix.sync.aligned.m8n8.x4.shared.b16 {%0,%1,%2,%3}, [%4];"
                 : "=r"(r[0]), "=r"(r[1]), "=r"(r[2]), "=r"(r[3]) : "r"(addr));
}
__device__ __forceinline__ void mma_bf16(float* c, const uint32_t* a, const uint32_t* b) {
    asm volatile("mma.sync.aligned.m16n8k16.row.col.f32.bf16.bf16.f32 "
        "{%0,%1,%2,%3}, {%4,%5,%6,%7}, {%8,%9}, {%0,%1,%2,%3};"
        : "+f"(c[0]), "+f"(c[1]), "+f"(c[2]), "+f"(c[3])
        : "r"(a[0]), "r"(a[1]), "r"(a[2]), "r"(a[3]), "r"(b[0]), "r"(b[1]));
}

// ---------------------------------------------------------------------
// fp32 -> bf16 hi/lo augmented operands (R14-identical).
// ---------------------------------------------------------------------
__device__ __forceinline__ void split4(float4 v, uint2& hi, uint2& lo) {
    const float* f = (const float*)&v;
    unsigned short h[4], l[4];
    #pragma unroll
    for (int i = 0; i < 4; i++) {
        __nv_bfloat16 hb = __float2bfloat16(f[i]);
        h[i] = __bfloat16_as_ushort(hb);
        l[i] = __bfloat16_as_ushort(__float2bfloat16(f[i] - __bfloat162float(hb)));
    }
    hi.x = (uint32_t)h[0] | ((uint32_t)h[1] << 16);
    hi.y = (uint32_t)h[2] | ((uint32_t)h[3] << 16);
    lo.x = (uint32_t)l[0] | ((uint32_t)l[1] << 16);
    lo.y = (uint32_t)l[2] | ((uint32_t)l[3] << 16);
}

#define CONV_A (AROWS * 256)
#define CONV_B (2 * HID * 256)

__global__ __launch_bounds__(256) void convert_bf16(
    const float* __restrict__ img, const float* __restrict__ attr,
    const float* __restrict__ W1)
{
    const int idx = blockIdx.x * 256 + threadIdx.x;
    if (idx < CONV_A) {
        const int r = idx >> 8, k = (idx & 255) * 4;
        float4 v = make_float4(0.f, 0.f, 0.f, 0.f);
        if (r < 128)      v = *(const float4*)&img[(size_t)r * FEAT + k];
        else if (r < 628) v = *(const float4*)&attr[(size_t)(r - 128) * FEAT + k];
        uint2 hi, lo; split4(v, hi, lo);
        *(uint2*)&g_A[(size_t)r * KP + k]        = hi;
        *(uint2*)&g_A[(size_t)r * KP + 1024 + k] = lo;
        *(uint2*)&g_A[(size_t)r * KP + 2048 + k] = hi;
    } else if (idx < CONV_A + CONV_B) {
        int j = idx - CONV_A;
        const int half = j >= HID * 256; if (half) j -= HID * 256;
        const int n = j >> 8, k = (j & 255) * 4;
        float4 v = *(const float4*)&W1[(size_t)n * (2 * FEAT) + half * FEAT + k];
        uint2 hi, lo; split4(v, hi, lo);
        unsigned short* Bp = g_B[half];
        *(uint2*)&Bp[(size_t)n * KP + k]        = hi;
        *(uint2*)&Bp[(size_t)n * KP + 1024 + k] = hi;
        *(uint2*)&Bp[(size_t)n * KP + 2048 + k] = lo;
    }
}

// ---------------------------------------------------------------------
// HMMA GEMM: D[64m x 32n] per block, 256 threads = 8 warps (4m x 2n),
// warp tile 16m x 16n. Same tiles/staging/fragments as R14; doubled warp
// count for latency hiding, halved per-thread accumulators.
// ---------------------------------------------------------------------
#define BLKM 64
#define BLKN 32
#define PADK 72          // 144B row stride: 16B-mult, conflict-free ldsm
#define NSLAB (KP / 64)  // 48

__global__ __launch_bounds__(256) void gemm_mma(const float* __restrict__ b1)
{
    __shared__ __align__(16) unsigned short As[2][BLKM][PADK];
    __shared__ __align__(16) unsigned short Bs[2][BLKN][PADK];

    const int tid  = threadIdx.x;
    const int lane = tid & 31;
    const int warp = tid >> 5;
    const int wm   = warp & 3;        // warp m (4) -> 16 rows
    const int wn   = warp >> 2;       // warp n (2) -> 16 cols
    const int by   = blockIdx.y;      // 10
    const int bx   = blockIdx.x;      // 16
    const bool is_img = (by < 2);

    const unsigned short* Aq = g_A + (size_t)(by * BLKM) * KP;
    const unsigned short* Bq = g_B[is_img ? 0 : 1] + (size_t)(bx * BLKN) * KP;

    const uint32_t asb = smem_u32(As);
    const uint32_t bsb = smem_u32(Bs);
    const uint32_t aRow =
        (uint32_t)((wm * 16 + (lane & 15)) * (PADK * 2) + (lane >> 4) * 16);
    const int n_l = wn * 16 + (lane & 7) + ((lane >> 4) << 3);
    const uint32_t bRow = (uint32_t)(n_l * (PADK * 2) + ((lane >> 3) & 1) * 16);

    float acc[2][4];
    #pragma unroll
    for (int j = 0; j < 2; j++)
        #pragma unroll
        for (int q = 0; q < 4; q++) acc[j][q] = 0.f;

    uint4 a_pf[2], b_pf;
    // prefetch slab 0
    #pragma unroll
    for (int i = 0; i < 2; i++) {
        const int id = i * 256 + tid;
        a_pf[i] = *(const uint4*)&Aq[(size_t)(id >> 3) * KP + (id & 7) * 8];
    }
    b_pf = *(const uint4*)&Bq[(size_t)(tid >> 3) * KP + (tid & 7) * 8];

    for (int it = 0; it < NSLAB; it++) {
        const int p = it & 1;
        #pragma unroll
        for (int i = 0; i < 2; i++) {
            const int id = i * 256 + tid;
            *(uint4*)&As[p][id >> 3][(id & 7) * 8] = a_pf[i];
        }
        *(uint4*)&Bs[p][tid >> 3][(tid & 7) * 8] = b_pf;
        __syncthreads();

        if (it + 1 < NSLAB) {          // prefetch next slab behind compute
            const int k0 = (it + 1) * 64;
            #pragma unroll
            for (int i = 0; i < 2; i++) {
                const int id = i * 256 + tid;
                a_pf[i] = *(const uint4*)&Aq[(size_t)(id >> 3) * KP + k0 + (id & 7) * 8];
            }
            b_pf = *(const uint4*)&Bq[(size_t)(tid >> 3) * KP + k0 + (tid & 7) * 8];
        }

        const uint32_t aBase = asb + (uint32_t)p * sizeof(As[0]);
        const uint32_t bBase = bsb + (uint32_t)p * sizeof(Bs[0]);
        #pragma unroll
        for (int ks = 0; ks < 4; ks++) {
            uint32_t af[4], bf[4];
            ldsm_x4(af, aBase + aRow + ks * 32);
            ldsm_x4(bf, bBase + bRow + ks * 32);   // NON-trans: B smem [n][k]
            mma_bf16(acc[0], af, bf + 0);
            mma_bf16(acc[1], af, bf + 2);
        }
        __syncthreads();
    }

    // writeout
    const int g  = lane >> 2;
    const int tc = (lane & 3) * 2;
    #pragma unroll
    for (int half = 0; half < 2; half++) {
        const int row = by * BLKM + wm * 16 + g + half * 8;
        #pragma unroll
        for (int nj = 0; nj < 2; nj++) {
            const int h = bx * BLKN + wn * 16 + nj * 8 + tc;
            const float v0 = acc[nj][half * 2 + 0];
            const float v1 = acc[nj][half * 2 + 1];
            if (is_img) {
                g_imgT[(h + 0) * BATCH + row] = v0 + __ldg(&b1[h]);
                g_imgT[(h + 1) * BATCH + row] = v1 + __ldg(&b1[h + 1]);
            } else {
                const int c = row - 128;
                g_attr[(size_t)c * HID + h]     = v0;   // buffer padded to 512 rows
                g_attr[(size_t)c * HID + h + 1] = v1;
            }
        }
    }
}

// ---------------------------------------------------------------------
// part[hs][c,b] = sum_{h chunk} relu(imgT[h,b] + attr[c,h]) * W2[h]  (R14)
// ---------------------------------------------------------------------
#define CT 8

__global__ __launch_bounds__(128) void relscore(const float* __restrict__ W2)
{
    __shared__ float attr8[HCH][CT];
    __shared__ float w2s[HCH];

    const int b  = threadIdx.x;
    const int c0 = blockIdx.x * CT;
    const int h0 = blockIdx.y * HCH;

    #pragma unroll
    for (int i = 0; i < CT; i++) {
        const int t  = i * 128 + b;
        const int cc = t >> 7, hh = t & 127;
        const int c  = c0 + cc;
        attr8[hh][cc] = (c < CLS) ? g_attr[(size_t)c * HID + h0 + hh] : 0.f;
    }
    w2s[b] = W2[h0 + b];
    __syncthreads();

    float acc[CT];
    #pragma unroll
    for (int i = 0; i < CT; i++) acc[i] = 0.f;

    const float* ip = g_imgT + (size_t)h0 * BATCH + b;

    #pragma unroll 8
    for (int hh = 0; hh < HCH; hh++) {
        const float iv = ip[(size_t)hh * BATCH];
        const float w  = w2s[hh];
        float4 a0 = *(float4*)&attr8[hh][0];
        float4 a1 = *(float4*)&attr8[hh][4];
        acc[0] += fmaxf(iv + a0.x, 0.f) * w;
        acc[1] += fmaxf(iv + a0.y, 0.f) * w;
        acc[2] += fmaxf(iv + a0.z, 0.f) * w;
        acc[3] += fmaxf(iv + a0.w, 0.f) * w;
        acc[4] += fmaxf(iv + a1.x, 0.f) * w;
        acc[5] += fmaxf(iv + a1.y, 0.f) * w;
        acc[6] += fmaxf(iv + a1.z, 0.f) * w;
        acc[7] += fmaxf(iv + a1.w, 0.f) * w;
    }

    float* part = g_part[blockIdx.y];
    #pragma unroll
    for (int cc = 0; cc < CT; cc++) {
        const int c = c0 + cc;
        if (c < CLS) part[c * BATCH + b] = acc[cc];
    }
}

__global__ __launch_bounds__(128) void finalize(float* __restrict__ out,
                                                const float* __restrict__ b2)
{
    const int b  = threadIdx.x;
    const int c0 = blockIdx.x * 4;
    const float bias = b2[0];

    float4 r;
    float* rv = (float*)&r;
    #pragma unroll
    for (int j = 0; j < 4; j++) {
        const int idx = (c0 + j) * BATCH + b;
        float s = bias;
        #pragma unroll
        for (int k = 0; k < HSPLIT; k++) s += g_part[k][idx];
        rv[j] = 1.f / (1.f + __expf(-s));
    }
    *(float4*)&out[(size_t)b * CLS + c0] = r;
}

// ---------------------------------------------------------------------
extern "C" void kernel_launch(void* const* d_in, const int* in_sizes, int n_in,
                              void* d_out, int out_size)
{
    const float* img  = (const float*)d_in[0];
    const float* attr = (const float*)d_in[1];
    const float* W1   = (const float*)d_in[2];
    const float* b1   = (const float*)d_in[3];
    const float* W2   = (const float*)d_in[4];
    const float* b2   = (const float*)d_in[5];
    float* out = (float*)d_out;

    convert_bf16<<<(CONV_A + CONV_B + 255) / 256, 256>>>(img, attr, W1);
    gemm_mma<<<dim3(HID / BLKN, AROWS / BLKM), 256>>>(b1);   // 160 blocks x 8 warps
    relscore<<<dim3((CLS + CT - 1) / CT, HSPLIT), 128>>>(W2);
    finalize<<<CLS / 4, 128>>>(out, b2);
}